// round 15
// baseline (speedup 1.0000x reference)
#include <cuda_runtime.h>
#include <cuda_bf16.h>
#include <cstdint>

typedef __nv_bfloat16 bf16;
typedef unsigned short ushortT;

constexpr int BG=4, SEQ=1024, CH=1024, HEADS=16, HDIM=64;
constexpr int ROWS = BG * SEQ;
constexpr long long BG_STRIDE  = (long long)SEQ * CH;
constexpr long long PROB_BATCH = (long long)SEQ * SEQ;

// ---- persistent bf16 hi/lo scratch (allocation-free rule) ----
__device__ __align__(256) bf16 g_Xqh[ROWS*CH], g_Xql[ROWS*CH];
__device__ __align__(256) bf16 g_Xkh[ROWS*CH], g_Xkl[ROWS*CH];
__device__ __align__(256) bf16 g_Wqh[CH*CH],  g_Wql[CH*CH];
__device__ __align__(256) bf16 g_Wkh[CH*CH],  g_Wkl[CH*CH];
__device__ __align__(256) bf16 g_Wvh[CH*CH],  g_Wvl[CH*CH];
__device__ __align__(256) bf16 g_Woh[CH*CH],  g_Wol[CH*CH];
__device__ __align__(256) bf16 g_Qh[ROWS*CH], g_Ql[ROWS*CH];
__device__ __align__(256) bf16 g_Kh[ROWS*CH], g_Kl[ROWS*CH];
__device__ __align__(256) bf16 g_Vh[ROWS*CH], g_Vl[ROWS*CH];
__device__ __align__(256) bf16 g_Ch[ROWS*CH], g_Cl[ROWS*CH];
__device__ float g_rowsum[BG*HEADS*SEQ];

// ---------------------------------------------------------------------------
// helpers
// ---------------------------------------------------------------------------
__device__ __forceinline__ uint32_t pack2(ushortT lo, ushortT hi) {
    return (uint32_t)lo | ((uint32_t)hi << 16);
}
__device__ __forceinline__ void bsplit(float x, ushortT& h, ushortT& l) {
    __nv_bfloat16 hb = __float2bfloat16_rn(x);
    h = __bfloat16_as_ushort(hb);
    l = __bfloat16_as_ushort(__float2bfloat16_rn(x - __bfloat162float(hb)));
}
__device__ __forceinline__ void ldmx4(uint32_t& r0, uint32_t& r1, uint32_t& r2, uint32_t& r3, uint32_t a) {
    asm volatile("ldmatrix.sync.aligned.m8n8.x4.shared.b16 {%0,%1,%2,%3},[%4];"
                 : "=r"(r0), "=r"(r1), "=r"(r2), "=r"(r3) : "r"(a));
}
__device__ __forceinline__ void ldmx4t(uint32_t& r0, uint32_t& r1, uint32_t& r2, uint32_t& r3, uint32_t a) {
    asm volatile("ldmatrix.sync.aligned.m8n8.x4.trans.shared.b16 {%0,%1,%2,%3},[%4];"
                 : "=r"(r0), "=r"(r1), "=r"(r2), "=r"(r3) : "r"(a));
}
__device__ __forceinline__ void mma16816(float* c, uint32_t a0, uint32_t a1, uint32_t a2, uint32_t a3,
                                         uint32_t b0, uint32_t b1) {
    asm volatile(
        "mma.sync.aligned.m16n8k16.row.col.f32.bf16.bf16.f32 "
        "{%0,%1,%2,%3},{%4,%5,%6,%7},{%8,%9},{%0,%1,%2,%3};"
        : "+f"(c[0]), "+f"(c[1]), "+f"(c[2]), "+f"(c[3])
        : "r"(a0), "r"(a1), "r"(a2), "r"(a3), "r"(b0), "r"(b1));
}
__device__ __forceinline__ void cpa16(uint32_t dst, const void* src) {
    asm volatile("cp.async.cg.shared.global [%0],[%1],16;" :: "r"(dst), "l"(src));
}
#define CP_COMMIT() asm volatile("cp.async.commit_group;")
#define CP_WAIT1()  asm volatile("cp.async.wait_group 1;")
#define CP_WAIT0()  asm volatile("cp.async.wait_group 0;")

// ---------------------------------------------------------------------------
// Dense GEMM machinery (unchanged from R14): 256 thr, 8 warps 4x2, 32x64 warp
// tiles, 3-stage ring, one barrier per k-tile, 3-sweep hi/lo compensation.
// ---------------------------------------------------------------------------
constexpr int ASTR = 24;
constexpr int A_SZ = 128 * ASTR;
constexpr int D_STG = 4 * A_SZ;
constexpr int SM_DENSE = 3 * D_STG * 2;

__device__ __forceinline__ void compute_tile(uint32_t sbase, int s, int wm, int wn,
                                             int lane, float acc[2][8][4])
{
    uint32_t s0 = sbase + (uint32_t)(s * D_STG) * 2;
    uint32_t ah[2][4], al[2][4];
    #pragma unroll
    for (int mt = 0; mt < 2; mt++) {
        int r = wm * 32 + mt * 16 + (lane & 15), c = (lane >> 4) << 3;
        ldmx4(ah[mt][0], ah[mt][1], ah[mt][2], ah[mt][3], s0 + (uint32_t)(r * ASTR + c) * 2);
        ldmx4(al[mt][0], al[mt][1], al[mt][2], al[mt][3], s0 + (uint32_t)(A_SZ + r * ASTR + c) * 2);
    }
    uint32_t b[8][2];
    #pragma unroll
    for (int p = 0; p < 4; p++) {
        int n = wn * 64 + p * 16 + (lane & 15), c = (lane >> 4) << 3;
        uint32_t r0, r1, r2, r3;
        ldmx4(r0, r1, r2, r3, s0 + (uint32_t)(2 * A_SZ + n * ASTR + c) * 2);
        b[2 * p][0] = r0; b[2 * p][1] = r2; b[2 * p + 1][0] = r1; b[2 * p + 1][1] = r3;
    }
    #pragma unroll
    for (int mt = 0; mt < 2; mt++)
        #pragma unroll
        for (int nt = 0; nt < 8; nt++)
            mma16816(acc[mt][nt], ah[mt][0], ah[mt][1], ah[mt][2], ah[mt][3], b[nt][0], b[nt][1]);
    #pragma unroll
    for (int mt = 0; mt < 2; mt++)
        #pragma unroll
        for (int nt = 0; nt < 8; nt++)
            mma16816(acc[mt][nt], al[mt][0], al[mt][1], al[mt][2], al[mt][3], b[nt][0], b[nt][1]);
    #pragma unroll
    for (int p = 0; p < 4; p++) {
        int n = wn * 64 + p * 16 + (lane & 15), c = (lane >> 4) << 3;
        uint32_t r0, r1, r2, r3;
        ldmx4(r0, r1, r2, r3, s0 + (uint32_t)(3 * A_SZ + n * ASTR + c) * 2);
        b[2 * p][0] = r0; b[2 * p][1] = r2; b[2 * p + 1][0] = r1; b[2 * p + 1][1] = r3;
    }
    #pragma unroll
    for (int mt = 0; mt < 2; mt++)
        #pragma unroll
        for (int nt = 0; nt < 8; nt++)
            mma16816(acc[mt][nt], ah[mt][0], ah[mt][1], ah[mt][2], ah[mt][3], b[nt][0], b[nt][1]);
}

template<int EPI>
__device__ __forceinline__ void gemm_body(
    const bf16* __restrict__ Ah, const bf16* __restrict__ Al,
    const bf16* __restrict__ Bh, const bf16* __restrict__ Bl,
    float* __restrict__ Cf, bf16* __restrict__ Coh, bf16* __restrict__ Col,
    const float* __restrict__ bias,
    int K, int lda, int ldb, int ldc, float scale, int row0, int col0)
{
    extern __shared__ bf16 sm[];
    const uint32_t sbase = (uint32_t)__cvta_generic_to_shared(sm);
    const int tid = threadIdx.x, lane = tid & 31, warp = tid >> 5;
    const int wm = warp >> 1, wn = warp & 1;

    auto loadS = [&](int kt, int s) {
        #pragma unroll
        for (int i = 0; i < 4; i++) {
            int e = tid + i * 256;
            int b = e >> 8, q = e & 255, row = q >> 1, ch = (q & 1) * 8;
            const bf16* base = (b == 0) ? Ah : (b == 1) ? Al : (b == 2) ? Bh : Bl;
            int rb = (b < 2) ? row0 : col0;
            int ld = (b < 2) ? lda : ldb;
            cpa16(sbase + (uint32_t)(s * D_STG + b * A_SZ + row * ASTR + ch) * 2,
                  base + (long long)(rb + row) * ld + kt * 16 + ch);
        }
        CP_COMMIT();
    };

    float acc[2][8][4];
    #pragma unroll
    for (int mt = 0; mt < 2; mt++)
        #pragma unroll
        for (int nt = 0; nt < 8; nt++)
            #pragma unroll
            for (int i = 0; i < 4; i++)
                acc[mt][nt][i] = 0.0f;

    const int NKI = K / 16;
    loadS(0, 0);
    if (NKI > 1) loadS(1, 1);
    for (int t = 0; t < NKI; t++) {
        if (t + 1 < NKI) CP_WAIT1(); else CP_WAIT0();
        __syncthreads();
        if (t + 2 < NKI) loadS(t + 2, (t + 2) % 3);
        compute_tile(sbase, t % 3, wm, wn, lane, acc);
    }

    #pragma unroll
    for (int mt = 0; mt < 2; mt++) {
        int r = row0 + wm * 32 + mt * 16 + (lane >> 2);
        #pragma unroll
        for (int nt = 0; nt < 8; nt++) {
            int c = col0 + wn * 64 + nt * 8 + ((lane & 3) << 1);
            float v0 = acc[mt][nt][0] * scale, v1 = acc[mt][nt][1] * scale;
            float v2 = acc[mt][nt][2] * scale, v3 = acc[mt][nt][3] * scale;
            float b0 = bias[c], b1 = bias[c + 1];
            if constexpr (EPI == 0) {
                *reinterpret_cast<float2*>(Cf + (long long)r * ldc + c)       = make_float2(v0 + b0, v1 + b1);
                *reinterpret_cast<float2*>(Cf + (long long)(r + 8) * ldc + c) = make_float2(v2 + b0, v3 + b1);
            } else {
                float x0 = v0 + b0, x1 = v1 + b1, x2 = v2 + b0, x3 = v3 + b1;
                ushortT h0, l0, h1, l1, h2, l2, h3, l3;
                bsplit(x0, h0, l0); bsplit(x1, h1, l1); bsplit(x2, h2, l2); bsplit(x3, h3, l3);
                *reinterpret_cast<uint32_t*>(Coh + (long long)r * ldc + c)       = pack2(h0, h1);
                *reinterpret_cast<uint32_t*>(Col + (long long)r * ldc + c)       = pack2(l0, l1);
                *reinterpret_cast<uint32_t*>(Coh + (long long)(r + 8) * ldc + c) = pack2(h2, h3);
                *reinterpret_cast<uint32_t*>(Col + (long long)(r + 8) * ldc + c) = pack2(l2, l3);
            }
        }
    }
}

struct ProjArgs {
    const bf16 *Ah[3], *Al[3], *Bh[3], *Bl[3];
    bf16 *Ch[3], *Cl[3];
    const float* bias[3];
};

__global__ __launch_bounds__(256, 2)
void proj_kernel(ProjArgs p)
{
    const int z = blockIdx.z;
    gemm_body<1>(p.Ah[z], p.Al[z], p.Bh[z], p.Bl[z],
                 nullptr, p.Ch[z], p.Cl[z], p.bias[z],
                 CH, CH, CH, CH, 1.0f, blockIdx.y * 128, blockIdx.x * 128);
}

__global__ __launch_bounds__(256, 2)
void out_kernel(const bf16* __restrict__ Ch, const bf16* __restrict__ Cl,
                const bf16* __restrict__ Wh, const bf16* __restrict__ Wl,
                float* __restrict__ out, const float* __restrict__ bo)
{
    gemm_body<0>(Ch, Cl, Wh, Wl, out, nullptr, nullptr, bo,
                 CH, CH, CH, CH, 1.0f, blockIdx.y * 128, blockIdx.x * 128);
}

// ---------------------------------------------------------------------------
// Fused fp32 -> bf16 hi/lo splits (6 tensors) + rowsum zeroing, one launch.
// ---------------------------------------------------------------------------
struct SplitAll {
    const float* src[6];
    bf16 *h[6], *l[6];
    float* rsum;
};

__global__ __launch_bounds__(256)
void split_all(SplitAll a)
{
    int bx = blockIdx.x, t; long long blk;
    if (bx < 4096)      { t = 0; blk = bx; }
    else if (bx < 8192) { t = 1; blk = bx - 4096; }
    else { int r = bx - 8192; t = 2 + (r >> 10); blk = r & 1023; }

    long long i = (blk * 256 + threadIdx.x) * 4;
    float4 v = *reinterpret_cast<const float4*>(a.src[t] + i);
    ushortT hh[4], ll[4];
    bsplit(v.x, hh[0], ll[0]); bsplit(v.y, hh[1], ll[1]);
    bsplit(v.z, hh[2], ll[2]); bsplit(v.w, hh[3], ll[3]);
    *reinterpret_cast<uint2*>(a.h[t] + i) = make_uint2(pack2(hh[0], hh[1]), pack2(hh[2], hh[3]));
    *reinterpret_cast<uint2*>(a.l[t] + i) = make_uint2(pack2(ll[0], ll[1]), pack2(ll[2], ll[3]));

    if (bx < 64) {
        int j = bx * 1024 + threadIdx.x * 4;
        *reinterpret_cast<float4*>(a.rsum + j) = make_float4(0.f, 0.f, 0.f, 0.f);
    }
}

// ---------------------------------------------------------------------------
// FUSED attention kernel: per CTA = (z, 128-row block), 512 threads, 16 warps
// (8x2: wm rows-of-16, wn col-halves). Q resident; K double-buffered; V single
// buffer; P (split probs) 128x128 hi/lo in smem.
// Phase 1: loop 8 col-tiles: S = QK^T (3-sweep), rowsum += exp(s/8). No output.
// Phase 2: loop 8 col-tiles: recompute S, w = exp(s/8)*inv; write P (fp32,
// the ONLY probs traffic); split w -> P smem; ctx += P.V (3-sweep).
// Epilogue: ctx -> bf16 hi/lo Ch/Cl.
// ---------------------------------------------------------------------------
constexpr int QSTR  = 72;                 // 144B rows: conflict-free ldmatrix(+trans)
constexpr int T64   = 128 * QSTR;         // 9216 elems per 128x64 matrix
constexpr int PSTR2 = 136;                // 272B rows: conflict-free for 128-wide P
constexpr int PT    = 128 * PSTR2;        // 17408
constexpr int OQ  = 0;
constexpr int OK0 = 2 * T64;              // 18432 (2 K bufs x (h+l))
constexpr int OV  = OK0 + 4 * T64;        // 55296
constexpr int OP  = OV + 2 * T64;         // 73728
constexpr int SM_FUSED = (OP + 2 * PT) * 2;   // 217088 B

__global__ __launch_bounds__(512, 1)
void fused_attn(const bf16* __restrict__ Qh, const bf16* __restrict__ Ql,
                const bf16* __restrict__ Kh, const bf16* __restrict__ Kl,
                const bf16* __restrict__ Vh, const bf16* __restrict__ Vl,
                float* __restrict__ probs,
                bf16* __restrict__ Coh, bf16* __restrict__ Col)
{
    extern __shared__ bf16 sm[];
    const uint32_t sb = (uint32_t)__cvta_generic_to_shared(sm);
    const int tid = threadIdx.x, lane = tid & 31, warp = tid >> 5;
    const int wm = warp >> 1, wn = warp & 1;
    const int z = blockIdx.z, zo = z >> 4, zi = z & 15;
    const int row0 = blockIdx.y * 128;
    const long long hoff = (long long)zo * BG_STRIDE + (long long)zi * HDIM;
    const bf16 *Qhz = Qh + hoff, *Qlz = Ql + hoff;
    const bf16 *Khz = Kh + hoff, *Klz = Kl + hoff;
    const bf16 *Vhz = Vh + hoff, *Vlz = Vl + hoff;
    float* Pz = probs + (long long)z * PROB_BATCH;

    // 128 rows x 8 chunks x 2 matrices = 2048 16B-chunks / 512 thr = 4 each
    auto cp64 = [&](const bf16* sH, const bf16* sL, int grow, int dstElem) {
        #pragma unroll
        for (int i = 0; i < 4; i++) {
            int e = tid + i * 512;
            int mat = e >> 10, q = e & 1023, row = q >> 3, ch = (q & 7) * 8;
            const bf16* src = (mat ? sL : sH) + (long long)(grow + row) * CH + ch;
            cpa16(sb + (uint32_t)(dstElem + mat * T64 + row * QSTR + ch) * 2, src);
        }
    };

    // S-mma for one 128x128 tile: accS[nt][4] per warp (16 x 64 slice)
    auto smma = [&](int kb, float (*accS)[4]) {
        #pragma unroll
        for (int nt = 0; nt < 8; nt++)
            #pragma unroll
            for (int i = 0; i < 4; i++)
                accS[nt][i] = 0.0f;
        const uint32_t kB = sb + (uint32_t)(OK0 + kb * 2 * T64) * 2;
        #pragma unroll
        for (int ks = 0; ks < 4; ks++) {
            int ar = wm * 16 + (lane & 15), ac = ks * 16 + ((lane >> 4) << 3);
            uint32_t q0, q1, q2, q3, u0, u1, u2, u3;
            ldmx4(q0, q1, q2, q3, sb + (uint32_t)(OQ + ar * QSTR + ac) * 2);
            ldmx4(u0, u1, u2, u3, sb + (uint32_t)(OQ + T64 + ar * QSTR + ac) * 2);
            uint32_t b[8][2];
            #pragma unroll
            for (int p = 0; p < 4; p++) {
                int n = wn * 64 + p * 16 + (lane & 15);
                uint32_t r0, r1, r2, r3;
                ldmx4(r0, r1, r2, r3, kB + (uint32_t)(n * QSTR + ac) * 2);
                b[2 * p][0] = r0; b[2 * p][1] = r2; b[2 * p + 1][0] = r1; b[2 * p + 1][1] = r3;
            }
            #pragma unroll
            for (int nt = 0; nt < 8; nt++)
                mma16816(accS[nt], q0, q1, q2, q3, b[nt][0], b[nt][1]);
            #pragma unroll
            for (int nt = 0; nt < 8; nt++)
                mma16816(accS[nt], u0, u1, u2, u3, b[nt][0], b[nt][1]);
            #pragma unroll
            for (int p = 0; p < 4; p++) {
                int n = wn * 64 + p * 16 + (lane & 15);
                uint32_t r0, r1, r2, r3;
                ldmx4(r0, r1, r2, r3, kB + (uint32_t)(T64 + n * QSTR + ac) * 2);
                b[2 * p][0] = r0; b[2 * p][1] = r2; b[2 * p + 1][0] = r1; b[2 * p + 1][1] = r3;
            }
            #pragma unroll
            for (int nt = 0; nt < 8; nt++)
                mma16816(accS[nt], q0, q1, q2, q3, b[nt][0], b[nt][1]);
        }
    };

    // PV-mma: P (smem, 128x128 hi/lo) x V (smem, 128x64 hi/lo) -> accC 16x32
    auto pvmma = [&](float (*accC)[4]) {
        #pragma unroll
        for (int ks = 0; ks < 8; ks++) {
            int pr = wm * 16 + (lane & 15), pc = ks * 16 + ((lane >> 4) << 3);
            uint32_t p0, p1, p2, p3, l0, l1, l2, l3;
            ldmx4(p0, p1, p2, p3, sb + (uint32_t)(OP + pr * PSTR2 + pc) * 2);
            ldmx4(l0, l1, l2, l3, sb + (uint32_t)(OP + PT + pr * PSTR2 + pc) * 2);
            uint32_t vb[4][2];
            #pragma unroll
            for (int p = 0; p < 2; p++) {
                int kr = ks * 16 + (lane & 7) + ((lane >> 4) << 3);
                int nc = wn * 32 + p * 16 + (((lane >> 3) & 1) << 3);
                uint32_t r0, r1, r2, r3;
                ldmx4t(r0, r1, r2, r3, sb + (uint32_t)(OV + kr * QSTR + nc) * 2);
                vb[2 * p][0] = r0; vb[2 * p][1] = r2; vb[2 * p + 1][0] = r1; vb[2 * p + 1][1] = r3;
            }
            #pragma unroll
            for (int nt = 0; nt < 4; nt++)
                mma16816(accC[nt], p0, p1, p2, p3, vb[nt][0], vb[nt][1]);
            #pragma unroll
            for (int nt = 0; nt < 4; nt++)
                mma16816(accC[nt], l0, l1, l2, l3, vb[nt][0], vb[nt][1]);
            #pragma unroll
            for (int p = 0; p < 2; p++) {
                int kr = ks * 16 + (lane & 7) + ((lane >> 4) << 3);
                int nc = wn * 32 + p * 16 + (((lane >> 3) & 1) << 3);
                uint32_t r0, r1, r2, r3;
                ldmx4t(r0, r1, r2, r3, sb + (uint32_t)(OV + T64 + kr * QSTR + nc) * 2);
                vb[2 * p][0] = r0; vb[2 * p][1] = r2; vb[2 * p + 1][0] = r1; vb[2 * p + 1][1] = r3;
            }
            #pragma unroll
            for (int nt = 0; nt < 4; nt++)
                mma16816(accC[nt], p0, p1, p2, p3, vb[nt][0], vb[nt][1]);
        }
    };

    float accS[8][4];

    // ---------------- Phase 1: rowsum ----------------
    cp64(Qhz, Qlz, row0, OQ);
    cp64(Khz, Klz, 0, OK0);           CP_COMMIT();        // group: Q + K0
    cp64(Khz, Klz, 128, OK0 + 2 * T64); CP_COMMIT();      // group: K1

    float rsA = 0.0f, rsB = 0.0f;
    for (int t = 0; t < 8; t++) {
        if (t + 1 < 8) CP_WAIT1(); else CP_WAIT0();       // K_t landed
        __syncthreads();
        smma(t & 1, accS);
        #pragma unroll
        for (int nt = 0; nt < 8; nt++) {
            rsA += __expf(accS[nt][0] * 0.125f) + __expf(accS[nt][1] * 0.125f);
            rsB += __expf(accS[nt][2] * 0.125f) + __expf(accS[nt][3] * 0.125f);
        }
        __syncthreads();                                  // all done reading K buf t&1
        if (t + 2 < 8) { cp64(Khz, Klz, (t + 2) * 128, OK0 + (t & 1) * 2 * T64); CP_COMMIT(); }
    }

    // cross-quad + cross-wn rowsum reduction via smem (reuses P area)
    rsA += __shfl_xor_sync(0xFFFFFFFFu, rsA, 1);
    rsA += __shfl_xor_sync(0xFFFFFFFFu, rsA, 2);
    rsB += __shfl_xor_sync(0xFFFFFFFFu, rsB, 1);
    rsB += __shfl_xor_sync(0xFFFFFFFFu, rsB, 2);
    float* rs = reinterpret_cast<float*>(sm + OP);
    if ((lane & 3) == 0) {
        rs[wn * 128 + wm * 16 + (lane >> 2)]     = rsA;
        rs[wn * 128 + wm * 16 + (lane >> 2) + 8] = rsB;
    }
    __syncthreads();
    const int rr = wm * 16 + (lane >> 2);
    const float invA = 1.0f / (rs[rr] + rs[128 + rr]);
    const float invB = 1.0f / (rs[rr + 8] + rs[128 + rr + 8]);
    __syncthreads();                                      // rs reads done before P STS

    // ---------------- Phase 2: P write + PV ----------------
    float accC[4][4];
    #pragma unroll
    for (int nt = 0; nt < 4; nt++)
        #pragma unroll
        for (int i = 0; i < 4; i++)
            accC[nt][i] = 0.0f;

    cp64(Khz, Klz, 0, OK0); CP_COMMIT();                  // pending: {K0}
    for (int t = 0; t < 8; t++) {
        CP_WAIT0();                                       // K_t landed (only pending)
        __syncthreads();                                  // V buf + P smem free (PV(t-1) done)
        cp64(Vhz, Vlz, t * 128, OV); CP_COMMIT();         // V_t (covered by S-mma)
        if (t + 1 < 8) { cp64(Khz, Klz, (t + 1) * 128, OK0 + ((t + 1) & 1) * 2 * T64); CP_COMMIT(); }
        smma(t & 1, accS);
        // w = exp(s/8)*inv: write P global + split into P smem
        #pragma unroll
        for (int nt = 0; nt < 8; nt++) {
            float w0 = __expf(accS[nt][0] * 0.125f) * invA;
            float w1 = __expf(accS[nt][1] * 0.125f) * invA;
            float w2 = __expf(accS[nt][2] * 0.125f) * invB;
            float w3 = __expf(accS[nt][3] * 0.125f) * invB;
            int cc = wn * 64 + nt * 8 + ((lane & 3) << 1);
            *reinterpret_cast<float2*>(Pz + (long long)(row0 + rr) * SEQ + t * 128 + cc)     = make_float2(w0, w1);
            *reinterpret_cast<float2*>(Pz + (long long)(row0 + rr + 8) * SEQ + t * 128 + cc) = make_float2(w2, w3);
            ushortT h0, lo0, h1, lo1, h2, lo2, h3, lo3;
            bsplit(w0, h0, lo0); bsplit(w1, h1, lo1); bsplit(w2, h2, lo2); bsplit(w3, h3, lo3);
            *reinterpret_cast<uint32_t*>(sm + OP + rr * PSTR2 + cc)            = pack2(h0, h1);
            *reinterpret_cast<uint32_t*>(sm + OP + (rr + 8) * PSTR2 + cc)      = pack2(h2, h3);
            *reinterpret_cast<uint32_t*>(sm + OP + PT + rr * PSTR2 + cc)       = pack2(lo0, lo1);
            *reinterpret_cast<uint32_t*>(sm + OP + PT + (rr + 8) * PSTR2 + cc) = pack2(lo2, lo3);
        }
        if (t + 1 < 8) CP_WAIT1(); else CP_WAIT0();       // V_t landed (K_{t+1} may pend)
        __syncthreads();                                  // P smem + V visible
        pvmma(accC);
    }

    // epilogue: ctx -> bf16 hi/lo
    bf16* Chz = Coh + hoff;
    bf16* Clz = Col + hoff;
    #pragma unroll
    for (int nt = 0; nt < 4; nt++) {
        int r = row0 + rr;
        int c = wn * 32 + nt * 8 + ((lane & 3) << 1);
        ushortT h0, lo0, h1, lo1, h2, lo2, h3, lo3;
        bsplit(accC[nt][0], h0, lo0); bsplit(accC[nt][1], h1, lo1);
        bsplit(accC[nt][2], h2, lo2); bsplit(accC[nt][3], h3, lo3);
        *reinterpret_cast<uint32_t*>(Chz + (long long)r * CH + c)       = pack2(h0, h1);
        *reinterpret_cast<uint32_t*>(Clz + (long long)r * CH + c)       = pack2(lo0, lo1);
        *reinterpret_cast<uint32_t*>(Chz + (long long)(r + 8) * CH + c) = pack2(h2, h3);
        *reinterpret_cast<uint32_t*>(Clz + (long long)(r + 8) * CH + c) = pack2(lo2, lo3);
    }
}

// ---------------------------------------------------------------------------
// Launch
// ---------------------------------------------------------------------------
extern "C" void kernel_launch(void* const* d_in, const int* in_sizes, int n_in,
                              void* d_out, int out_size)
{
    const float* xq  = (const float*)d_in[0];
    const float* xkv = (const float*)d_in[1];
    const float* Wq  = (const float*)d_in[2];
    const float* bq  = (const float*)d_in[3];
    const float* Wk  = (const float*)d_in[4];
    const float* bk  = (const float*)d_in[5];
    const float* Wv  = (const float*)d_in[6];
    const float* bv  = (const float*)d_in[7];
    const float* Wo  = (const float*)d_in[8];
    const float* bo  = (const float*)d_in[9];

    float* out   = (float*)d_out;
    float* probs = out + (long long)ROWS * CH;

    bf16 *Xqh, *Xql, *Xkh, *Xkl, *Wqh, *Wql, *Wkh, *Wkl, *Wvh, *Wvl, *Woh, *Wol;
    bf16 *Qh, *Ql, *Kh, *Kl, *Vh, *Vl, *Ch, *Cl;
    float* rsum;
    cudaGetSymbolAddress((void**)&Xqh, g_Xqh); cudaGetSymbolAddress((void**)&Xql, g_Xql);
    cudaGetSymbolAddress((void**)&Xkh, g_Xkh); cudaGetSymbolAddress((void**)&Xkl, g_Xkl);
    cudaGetSymbolAddress((void**)&Wqh, g_Wqh); cudaGetSymbolAddress((void**)&Wql, g_Wql);
    cudaGetSymbolAddress((void**)&Wkh, g_Wkh); cudaGetSymbolAddress((void**)&Wkl, g_Wkl);
    cudaGetSymbolAddress((void**)&Wvh, g_Wvh); cudaGetSymbolAddress((void**)&Wvl, g_Wvl);
    cudaGetSymbolAddress((void**)&Woh, g_Woh); cudaGetSymbolAddress((void**)&Wol, g_Wol);
    cudaGetSymbolAddress((void**)&Qh, g_Qh);   cudaGetSymbolAddress((void**)&Ql, g_Ql);
    cudaGetSymbolAddress((void**)&Kh, g_Kh);   cudaGetSymbolAddress((void**)&Kl, g_Kl);
    cudaGetSymbolAddress((void**)&Vh, g_Vh);   cudaGetSymbolAddress((void**)&Vl, g_Vl);
    cudaGetSymbolAddress((void**)&Ch, g_Ch);   cudaGetSymbolAddress((void**)&Cl, g_Cl);
    cudaGetSymbolAddress((void**)&rsum, g_rowsum);

    cudaFuncSetAttribute((const void*)proj_kernel, cudaFuncAttributeMaxDynamicSharedMemorySize, SM_DENSE);
    cudaFuncSetAttribute((const void*)out_kernel,  cudaFuncAttributeMaxDynamicSharedMemorySize, SM_DENSE);
    cudaFuncSetAttribute((const void*)fused_attn,  cudaFuncAttributeMaxDynamicSharedMemorySize, SM_FUSED);

    // 0. fused splits + rowsum zeroing
    SplitAll sa;
    sa.src[0] = xq;  sa.h[0] = Xqh; sa.l[0] = Xql;
    sa.src[1] = xkv; sa.h[1] = Xkh; sa.l[1] = Xkl;
    sa.src[2] = Wq;  sa.h[2] = Wqh; sa.l[2] = Wql;
    sa.src[3] = Wk;  sa.h[3] = Wkh; sa.l[3] = Wkl;
    sa.src[4] = Wv;  sa.h[4] = Wvh; sa.l[4] = Wvl;
    sa.src[5] = Wo;  sa.h[5] = Woh; sa.l[5] = Wol;
    sa.rsum = rsum;
    split_all<<<2 * 4096 + 4 * 1024, 256>>>(sa);

    // 1. fused Q/K/V projections
    ProjArgs pa;
    pa.Ah[0] = Xqh; pa.Al[0] = Xql; pa.Bh[0] = Wqh; pa.Bl[0] = Wql; pa.Ch[0] = Qh; pa.Cl[0] = Ql; pa.bias[0] = bq;
    pa.Ah[1] = Xkh; pa.Al[1] = Xkl; pa.Bh[1] = Wkh; pa.Bl[1] = Wkl; pa.Ch[1] = Kh; pa.Cl[1] = Kl; pa.bias[1] = bk;
    pa.Ah[2] = Xkh; pa.Al[2] = Xkl; pa.Bh[2] = Wvh; pa.Bl[2] = Wvl; pa.Ch[2] = Vh; pa.Cl[2] = Vl; pa.bias[2] = bv;
    proj_kernel<<<dim3(CH / 128, ROWS / 128, 3), 256, SM_DENSE>>>(pa);

    // 2. fused attention: rowsum pass + (P write + PV) pass
    fused_attn<<<dim3(1, SEQ / 128, BG * HEADS), 512, SM_FUSED>>>(
        Qh, Ql, Kh, Kl, Vh, Vl, probs, Ch, Cl);

    // 3. output projection
    out_kernel<<<dim3(CH / 128, ROWS / 128, 1), 256, SM_DENSE>>>(Ch, Cl, Woh, Wol, out, bo);
}